// round 3
// baseline (speedup 1.0000x reference)
#include <cuda_runtime.h>
#include <math.h>

// ---------------- problem constants ----------------
#define D_MODEL   256
#define N_HEADS   8
#define HEAD_DIM  32
#define N_LEVELS  4
#define N_POINTS  4
#define L_TOK     13294
#define BATCH     4
#define M_TOT     (BATCH * L_TOK)   // 53176
#define D_FFN     1024

// ---------------- scratch (static device globals; no allocations) ----------------
__device__ float g_q    [(size_t)M_TOT * D_MODEL];
__device__ float g_mem  [(size_t)M_TOT * D_MODEL];
__device__ float g_value[(size_t)M_TOT * D_MODEL];
__device__ float g_offs [(size_t)M_TOT * D_MODEL];
__device__ float g_awlog[(size_t)M_TOT * 128];
__device__ float g_acc  [(size_t)M_TOT * D_MODEL];
__device__ float g_attn [(size_t)M_TOT * D_MODEL];
__device__ float g_x    [(size_t)M_TOT * D_MODEL];
__device__ float g_h    [(size_t)M_TOT * D_FFN];
__device__ float g_ffn  [(size_t)M_TOT * D_MODEL];

// ---------------- elementwise add (q = src+pos, mem = src2+mempos) ----------------
__global__ void add2_kernel(const float* __restrict__ a, const float* __restrict__ b,
                            float* __restrict__ o, int n4)
{
    int i = blockIdx.x * blockDim.x + threadIdx.x;
    if (i < n4) {
        float4 x = ((const float4*)a)[i];
        float4 y = ((const float4*)b)[i];
        x.x += y.x; x.y += y.y; x.z += y.z; x.w += y.w;
        ((float4*)o)[i] = x;
    }
}

// ---------------- SGEMM: C[M,N] = A[M,K] @ W[K,N] + bias (opt ReLU) ----------------
// Block tile 128x64, BK=16, 256 threads, 8x4 per-thread tile.
// As stored transposed so the 8-row slab per thread is contiguous -> LDS.128.
template<int RELU>
__global__ __launch_bounds__(256)
void sgemm_kernel(const float* __restrict__ A, const float* __restrict__ W,
                  const float* __restrict__ bias, float* __restrict__ C,
                  int M, int N, int K)
{
    const int BM = 128, BN = 64, BK = 16;
    __shared__ float As[BK * BM];   // transposed: As[k][m]
    __shared__ float Bs[BK * BN];   // Bs[k][n]

    int tid = threadIdx.x;
    int m0 = blockIdx.y * BM;
    int n0 = blockIdx.x * BN;
    int tr = tid >> 4;   // 0..15 -> rows tr*8..tr*8+7
    int tc = tid & 15;   // 0..15 -> cols tc*4..tc*4+3

    float acc[8][4];
#pragma unroll
    for (int i = 0; i < 8; i++)
#pragma unroll
        for (int j = 0; j < 4; j++) acc[i][j] = 0.0f;

    for (int k0 = 0; k0 < K; k0 += BK) {
        // load A tile (128 rows x 16 k) as float4, store transposed
#pragma unroll
        for (int it = 0; it < 2; it++) {
            int idx = tid + it * 256;      // 0..511
            int row = idx >> 2;            // 0..127
            int kq  = idx & 3;             // float4 slot along k
            float4 v = make_float4(0.f, 0.f, 0.f, 0.f);
            if (m0 + row < M)
                v = *(const float4*)(A + (size_t)(m0 + row) * K + k0 + kq * 4);
            As[(kq * 4 + 0) * BM + row] = v.x;
            As[(kq * 4 + 1) * BM + row] = v.y;
            As[(kq * 4 + 2) * BM + row] = v.z;
            As[(kq * 4 + 3) * BM + row] = v.w;
        }
        // load B tile (16 k x 64 n) as float4
        {
            int kk = tid >> 4;             // 0..15
            int cq = tid & 15;             // 0..15 float4 slots
            float4 v = *(const float4*)(W + (size_t)(k0 + kk) * N + n0 + cq * 4);
            *(float4*)(Bs + kk * BN + cq * 4) = v;
        }
        __syncthreads();

#pragma unroll
        for (int k = 0; k < BK; k++) {
            // vectorized smem reads: 2x LDS.128 for A slab, 1x LDS.128 for B
            float4 a0 = *(const float4*)(As + k * BM + tr * 8);
            float4 a1 = *(const float4*)(As + k * BM + tr * 8 + 4);
            float4 b0 = *(const float4*)(Bs + k * BN + tc * 4);
            float ra[8] = {a0.x, a0.y, a0.z, a0.w, a1.x, a1.y, a1.z, a1.w};
            float rb[4] = {b0.x, b0.y, b0.z, b0.w};
#pragma unroll
            for (int i = 0; i < 8; i++)
#pragma unroll
                for (int j = 0; j < 4; j++)
                    acc[i][j] = fmaf(ra[i], rb[j], acc[i][j]);
        }
        __syncthreads();
    }

    // epilogue: bias (+ relu) + store
    float4 bv = *(const float4*)(bias + n0 + tc * 4);
#pragma unroll
    for (int i = 0; i < 8; i++) {
        int m = m0 + tr * 8 + i;
        if (m < M) {
            float4 o;
            o.x = acc[i][0] + bv.x;
            o.y = acc[i][1] + bv.y;
            o.z = acc[i][2] + bv.z;
            o.w = acc[i][3] + bv.w;
            if (RELU) {
                o.x = fmaxf(o.x, 0.f); o.y = fmaxf(o.y, 0.f);
                o.z = fmaxf(o.z, 0.f); o.w = fmaxf(o.w, 0.f);
            }
            *(float4*)(C + (size_t)m * N + n0 + tc * 4) = o;
        }
    }
}

// ---------------- deformable attention sampling ----------------
// One block per (b, q): 8 warps = 8 heads, lane = channel (HEAD_DIM=32).
__global__ __launch_bounds__(256)
void deform_sample_kernel(const float* __restrict__ value,
                          const float* __restrict__ offs,
                          const float* __restrict__ awlog,
                          float* __restrict__ acc)
{
    const int bq = blockIdx.x;                // 0..M_TOT-1
    if (bq >= M_TOT) return;
    const int h    = threadIdx.x >> 5;        // head
    const int lane = threadIdx.x & 31;        // channel

    const int b  = bq / L_TOK;
    const int qi = bq - b * L_TOK;

    // query's own level -> reference point
    int ql, s;
    if      (qi < 10000) { ql = 0; s = 0;     }
    else if (qi < 12500) { ql = 1; s = 10000; }
    else if (qi < 13125) { ql = 2; s = 12500; }
    else                 { ql = 3; s = 13125; }
    const int HS[4] = {100, 50, 25, 13};
    const int Wq = HS[ql];
    int rem = qi - s;
    float refx = ((rem % Wq) + 0.5f) / (float)Wq;
    float refy = ((rem / Wq) + 0.5f) / (float)Wq;   // H==W per level

    // softmax over 16 (level,point) logits for this head
    float e[16];
    {
        const float4* lg = (const float4*)(awlog + (size_t)bq * 128 + h * 16);
        float4 t0 = lg[0], t1 = lg[1], t2 = lg[2], t3 = lg[3];
        e[0]=t0.x; e[1]=t0.y; e[2]=t0.z; e[3]=t0.w;
        e[4]=t1.x; e[5]=t1.y; e[6]=t1.z; e[7]=t1.w;
        e[8]=t2.x; e[9]=t2.y; e[10]=t2.z; e[11]=t2.w;
        e[12]=t3.x; e[13]=t3.y; e[14]=t3.z; e[15]=t3.w;
        float m = e[0];
#pragma unroll
        for (int j = 1; j < 16; j++) m = fmaxf(m, e[j]);
        float ssum = 0.f;
#pragma unroll
        for (int j = 0; j < 16; j++) { e[j] = expf(e[j] - m); ssum += e[j]; }
        float inv = 1.0f / ssum;
#pragma unroll
        for (int j = 0; j < 16; j++) e[j] *= inv;
    }

    const float* off   = offs  + (size_t)bq * 256 + h * 32;      // [4][4][2]
    const float* vbase = value + (size_t)b * L_TOK * 256 + h * 32 + lane;

    const int   LH[4]  = {100, 50, 25, 13};
    const int   LS[4]  = {0, 10000, 12500, 13125};

    float a = 0.0f;
#pragma unroll
    for (int l = 0; l < 4; l++) {
        const int   Wl = LH[l];
        const int   Sl = LS[l];
        const float Wf = (float)Wl;
#pragma unroll
        for (int p = 0; p < 4; p++) {
            float ox = off[(l * 4 + p) * 2 + 0];
            float oy = off[(l * 4 + p) * 2 + 1];
            float aw = e[l * 4 + p];
            // loc = ref + off/W ; x = loc*W - 0.5 (same fp order as reference)
            float locx = refx + ox / Wf;
            float locy = refy + oy / Wf;
            float x = locx * Wf - 0.5f;
            float y = locy * Wf - 0.5f;
            float x0f = floorf(x), y0f = floorf(y);
            float wx1 = x - x0f,   wy1 = y - y0f;
            float wx0 = 1.0f - wx1, wy0 = 1.0f - wy1;
            int ix0 = (int)x0f, iy0 = (int)y0f;
            int ix1 = ix0 + 1,  iy1 = iy0 + 1;
            bool vx0 = (ix0 >= 0) & (ix0 < Wl);
            bool vx1 = (ix1 >= 0) & (ix1 < Wl);
            bool vy0 = (iy0 >= 0) & (iy0 < Wl);
            bool vy1 = (iy1 >= 0) & (iy1 < Wl);

            if (vy0 & vx0) a = fmaf(vbase[(size_t)(Sl + iy0 * Wl + ix0) * 256], wy0 * wx0 * aw, a);
            if (vy0 & vx1) a = fmaf(vbase[(size_t)(Sl + iy0 * Wl + ix1) * 256], wy0 * wx1 * aw, a);
            if (vy1 & vx0) a = fmaf(vbase[(size_t)(Sl + iy1 * Wl + ix0) * 256], wy1 * wx0 * aw, a);
            if (vy1 & vx1) a = fmaf(vbase[(size_t)(Sl + iy1 * Wl + ix1) * 256], wy1 * wx1 * aw, a);
        }
    }
    acc[(size_t)bq * 256 + h * 32 + lane] = a;
}

// ---------------- fused residual + LayerNorm ----------------
// out = LN(a + r) * g + b ; one warp per row of 256.
__global__ __launch_bounds__(256)
void ln_kernel(const float* __restrict__ a, const float* __restrict__ r,
               const float* __restrict__ g, const float* __restrict__ be,
               float* __restrict__ out)
{
    int row  = blockIdx.x * 8 + (threadIdx.x >> 5);
    int lane = threadIdx.x & 31;
    if (row >= M_TOT) return;

    const float4* pa = (const float4*)(a + (size_t)row * 256);
    const float4* pr = (const float4*)(r + (size_t)row * 256);
    float4 v0 = pa[lane],      w0 = pr[lane];
    float4 v1 = pa[32 + lane], w1 = pr[32 + lane];
    v0.x += w0.x; v0.y += w0.y; v0.z += w0.z; v0.w += w0.w;
    v1.x += w1.x; v1.y += w1.y; v1.z += w1.z; v1.w += w1.w;

    float ssum = v0.x + v0.y + v0.z + v0.w + v1.x + v1.y + v1.z + v1.w;
#pragma unroll
    for (int o = 16; o; o >>= 1) ssum += __shfl_xor_sync(0xFFFFFFFFu, ssum, o);
    float mu = ssum * (1.0f / 256.0f);

    float d0x = v0.x - mu, d0y = v0.y - mu, d0z = v0.z - mu, d0w = v0.w - mu;
    float d1x = v1.x - mu, d1y = v1.y - mu, d1z = v1.z - mu, d1w = v1.w - mu;
    float sq = d0x*d0x + d0y*d0y + d0z*d0z + d0w*d0w
             + d1x*d1x + d1y*d1y + d1z*d1z + d1w*d1w;
#pragma unroll
    for (int o = 16; o; o >>= 1) sq += __shfl_xor_sync(0xFFFFFFFFu, sq, o);
    float var = sq * (1.0f / 256.0f);
    float sc = rsqrtf(var + 1e-5f);

    const float4* pg = (const float4*)g;
    const float4* pb = (const float4*)be;
    float4 g0 = pg[lane], g1 = pg[32 + lane];
    float4 b0 = pb[lane], b1 = pb[32 + lane];

    float4 o0, o1;
    o0.x = d0x * sc * g0.x + b0.x;  o0.y = d0y * sc * g0.y + b0.y;
    o0.z = d0z * sc * g0.z + b0.z;  o0.w = d0w * sc * g0.w + b0.w;
    o1.x = d1x * sc * g1.x + b1.x;  o1.y = d1y * sc * g1.y + b1.y;
    o1.z = d1z * sc * g1.z + b1.z;  o1.w = d1w * sc * g1.w + b1.w;

    float4* po = (float4*)(out + (size_t)row * 256);
    po[lane]      = o0;
    po[32 + lane] = o1;
}

// ---------------- launch ----------------
extern "C" void kernel_launch(void* const* d_in, const int* in_sizes, int n_in,
                              void* d_out, int out_size)
{
    const float* src        = (const float*)d_in[0];
    const float* src2       = (const float*)d_in[1];
    const float* pos        = (const float*)d_in[2];
    const float* memory_pos = (const float*)d_in[3];
    const float* value_w    = (const float*)d_in[4];
    const float* value_b    = (const float*)d_in[5];
    const float* off_w      = (const float*)d_in[6];
    const float* off_b      = (const float*)d_in[7];
    const float* aw_w       = (const float*)d_in[8];
    const float* aw_b       = (const float*)d_in[9];
    const float* out_w      = (const float*)d_in[10];
    const float* out_b      = (const float*)d_in[11];
    const float* ln_g       = (const float*)d_in[12];
    const float* ln_b       = (const float*)d_in[13];
    const float* lin1_w     = (const float*)d_in[14];
    const float* lin1_b     = (const float*)d_in[15];
    const float* lin2_w     = (const float*)d_in[16];
    const float* lin2_b     = (const float*)d_in[17];
    float* outp = (float*)d_out;

    float *q, *mem, *value, *offs, *awlog, *acc, *attn, *x, *hbuf, *ffn;
    cudaGetSymbolAddress((void**)&q,     g_q);
    cudaGetSymbolAddress((void**)&mem,   g_mem);
    cudaGetSymbolAddress((void**)&value, g_value);
    cudaGetSymbolAddress((void**)&offs,  g_offs);
    cudaGetSymbolAddress((void**)&awlog, g_awlog);
    cudaGetSymbolAddress((void**)&acc,   g_acc);
    cudaGetSymbolAddress((void**)&attn,  g_attn);
    cudaGetSymbolAddress((void**)&x,     g_x);
    cudaGetSymbolAddress((void**)&hbuf,  g_h);
    cudaGetSymbolAddress((void**)&ffn,   g_ffn);

    const int n4 = M_TOT * D_MODEL / 4;
    add2_kernel<<<(n4 + 255) / 256, 256>>>(src,  pos,        q,   n4);
    add2_kernel<<<(n4 + 255) / 256, 256>>>(src2, memory_pos, mem, n4);

    dim3 blk(256);
    dim3 g256(256 / 64, (M_TOT + 127) / 128);   // N=256
    dim3 g128(128 / 64, (M_TOT + 127) / 128);   // N=128
    dim3 g1024(1024 / 64, (M_TOT + 127) / 128); // N=1024

    sgemm_kernel<0><<<g256, blk>>>(mem, value_w, value_b, value, M_TOT, 256, 256);
    sgemm_kernel<0><<<g256, blk>>>(q,   off_w,   off_b,   offs,  M_TOT, 256, 256);
    sgemm_kernel<0><<<g128, blk>>>(q,   aw_w,    aw_b,    awlog, M_TOT, 128, 256);

    deform_sample_kernel<<<M_TOT, 256>>>(value, offs, awlog, acc);

    sgemm_kernel<0><<<g256, blk>>>(acc, out_w, out_b, attn, M_TOT, 256, 256);

    ln_kernel<<<(M_TOT + 7) / 8, 256>>>(attn, src, ln_g, ln_b, x);

    sgemm_kernel<1><<<g1024, blk>>>(x,    lin1_w, lin1_b, hbuf, M_TOT, 1024, 256);
    sgemm_kernel<0><<<g256,  blk>>>(hbuf, lin2_w, lin2_b, ffn,  M_TOT, 256, 1024);

    ln_kernel<<<(M_TOT + 7) / 8, 256>>>(ffn, x, ln_g, ln_b, outp);
}

// round 5
// speedup vs baseline: 2.0182x; 2.0182x over previous
#include <cuda_runtime.h>
#include <math.h>
#include <stdint.h>

// ---------------- problem constants ----------------
#define D_MODEL   256
#define N_HEADS   8
#define HEAD_DIM  32
#define L_TOK     13294
#define BATCH     4
#define M_TOT     (BATCH * L_TOK)   // 53176
#define D_FFN     1024

// ---------------- scratch (static device globals; no allocations) ----------------
__device__ float g_q    [(size_t)M_TOT * D_MODEL];
__device__ float g_mem  [(size_t)M_TOT * D_MODEL];
__device__ float g_value[(size_t)M_TOT * D_MODEL];
__device__ float g_offs [(size_t)M_TOT * D_MODEL];
__device__ float g_awlog[(size_t)M_TOT * 128];
__device__ float g_acc  [(size_t)M_TOT * D_MODEL];
__device__ float g_attn [(size_t)M_TOT * D_MODEL];
__device__ float g_x    [(size_t)M_TOT * D_MODEL];
__device__ float g_h    [(size_t)M_TOT * D_FFN];
__device__ float g_ffn  [(size_t)M_TOT * D_MODEL];

// ---------------- helpers ----------------
__device__ __forceinline__ float to_tf32(float x) {
    uint32_t u;
    asm("cvt.rna.tf32.f32 %0, %1;" : "=r"(u) : "f"(x));
    return __uint_as_float(u);
}

__device__ __forceinline__ void mma_tf32(float* c, const uint32_t* a, const uint32_t* b) {
    asm volatile(
        "mma.sync.aligned.m16n8k8.row.col.f32.tf32.tf32.f32 "
        "{%0,%1,%2,%3}, {%4,%5,%6,%7}, {%8,%9}, {%0,%1,%2,%3};\n"
        : "+f"(c[0]), "+f"(c[1]), "+f"(c[2]), "+f"(c[3])
        : "r"(a[0]), "r"(a[1]), "r"(a[2]), "r"(a[3]),
          "r"(b[0]), "r"(b[1]));
}

// ---------------- elementwise add ----------------
__global__ void add2_kernel(const float* __restrict__ a, const float* __restrict__ b,
                            float* __restrict__ o, int n4)
{
    int i = blockIdx.x * blockDim.x + threadIdx.x;
    if (i < n4) {
        float4 x = ((const float4*)a)[i];
        float4 y = ((const float4*)b)[i];
        x.x += y.x; x.y += y.y; x.z += y.z; x.w += y.w;
        ((float4*)o)[i] = x;
    }
}

// ---------------- TF32 tensor-core GEMM ----------------
// C[M,N] = A[M,K] @ W[K,N] + bias (opt ReLU)
// Block tile 128x128x32, 256 threads (8 warps: 2m x 4n), warp tile 64x32,
// fragments m16n8k8 tf32. A smem [m][k] lda=36, B smem [k][n] ldb=136
// (paddings chosen for conflict-free fragment LDS).
template<int RELU>
__global__ __launch_bounds__(256)
void tgemm_kernel(const float* __restrict__ A, const float* __restrict__ W,
                  const float* __restrict__ bias, float* __restrict__ C,
                  int M, int N, int K)
{
    const int BM = 128, BN = 128, BK = 32;
    const int LDA = 36, LDB = 136;
    __shared__ float As[BM * LDA];   // [m][k]
    __shared__ float Bs[BK * LDB];   // [k][n]

    const int tid  = threadIdx.x;
    const int lane = tid & 31;
    const int warp = tid >> 5;
    const int wm = (warp >> 2) * 64;   // warp m offset (0 or 64)
    const int wn = (warp & 3) * 32;    // warp n offset (0,32,64,96)
    const int grp = lane >> 2;         // 0..7
    const int tg  = lane & 3;          // 0..3
    const int m0 = blockIdx.y * BM;
    const int n0 = blockIdx.x * BN;

    float acc[4][4][4];
#pragma unroll
    for (int mi = 0; mi < 4; mi++)
#pragma unroll
        for (int ni = 0; ni < 4; ni++)
#pragma unroll
            for (int e = 0; e < 4; e++) acc[mi][ni][e] = 0.0f;

    for (int k0 = 0; k0 < K; k0 += BK) {
        // ---- fill A tile: 128 rows x 32 k = 1024 float4, 4 per thread
#pragma unroll
        for (int it = 0; it < 4; it++) {
            int idx = tid + it * 256;
            int r  = idx >> 3;          // 0..127
            int kq = idx & 7;           // float4 slot along k
            float4 v = make_float4(0.f, 0.f, 0.f, 0.f);
            if (m0 + r < M)
                v = *(const float4*)(A + (size_t)(m0 + r) * K + k0 + kq * 4);
            v.x = to_tf32(v.x); v.y = to_tf32(v.y);
            v.z = to_tf32(v.z); v.w = to_tf32(v.w);
            *(float4*)(As + r * LDA + kq * 4) = v;
        }
        // ---- fill B tile: 32 k x 128 n = 1024 float4, 4 per thread
#pragma unroll
        for (int it = 0; it < 4; it++) {
            int idx = tid + it * 256;
            int kk = idx >> 5;          // 0..31
            int cq = idx & 31;          // float4 slot along n
            float4 v = *(const float4*)(W + (size_t)(k0 + kk) * N + n0 + cq * 4);
            v.x = to_tf32(v.x); v.y = to_tf32(v.y);
            v.z = to_tf32(v.z); v.w = to_tf32(v.w);
            *(float4*)(Bs + kk * LDB + cq * 4) = v;
        }
        __syncthreads();

#pragma unroll
        for (int ks = 0; ks < 4; ks++) {
            const int kb = ks * 8;
            uint32_t a[4][4], b[4][2];
#pragma unroll
            for (int mi = 0; mi < 4; mi++) {
                const float* ap = As + (wm + mi * 16 + grp) * LDA + kb + tg;
                a[mi][0] = __float_as_uint(ap[0]);
                a[mi][2] = __float_as_uint(ap[4]);
                a[mi][1] = __float_as_uint(ap[8 * LDA]);
                a[mi][3] = __float_as_uint(ap[8 * LDA + 4]);
            }
#pragma unroll
            for (int ni = 0; ni < 4; ni++) {
                const float* bp = Bs + (kb + tg) * LDB + wn + ni * 8 + grp;
                b[ni][0] = __float_as_uint(bp[0]);
                b[ni][1] = __float_as_uint(bp[4 * LDB]);
            }
#pragma unroll
            for (int mi = 0; mi < 4; mi++)
#pragma unroll
                for (int ni = 0; ni < 4; ni++)
                    mma_tf32(acc[mi][ni], a[mi], b[ni]);
        }
        __syncthreads();
    }

    // ---- epilogue: bias (+relu), float2 stores
#pragma unroll
    for (int mi = 0; mi < 4; mi++) {
        int r0 = m0 + wm + mi * 16 + grp;
        int r1 = r0 + 8;
#pragma unroll
        for (int ni = 0; ni < 4; ni++) {
            int col = n0 + wn + ni * 8 + tg * 2;
            float bx = bias[col], by = bias[col + 1];
            float* cc = acc[mi][ni];
            if (r0 < M) {
                float2 o; o.x = cc[0] + bx; o.y = cc[1] + by;
                if (RELU) { o.x = fmaxf(o.x, 0.f); o.y = fmaxf(o.y, 0.f); }
                *(float2*)(C + (size_t)r0 * N + col) = o;
            }
            if (r1 < M) {
                float2 o; o.x = cc[2] + bx; o.y = cc[3] + by;
                if (RELU) { o.x = fmaxf(o.x, 0.f); o.y = fmaxf(o.y, 0.f); }
                *(float2*)(C + (size_t)r1 * N + col) = o;
            }
        }
    }
}

// ---------------- deformable attention sampling ----------------
__global__ __launch_bounds__(256)
void deform_sample_kernel(const float* __restrict__ value,
                          const float* __restrict__ offs,
                          const float* __restrict__ awlog,
                          float* __restrict__ acc)
{
    const int bq = blockIdx.x;
    if (bq >= M_TOT) return;
    const int h    = threadIdx.x >> 5;
    const int lane = threadIdx.x & 31;

    const int b  = bq / L_TOK;
    const int qi = bq - b * L_TOK;

    int ql, s;
    if      (qi < 10000) { ql = 0; s = 0;     }
    else if (qi < 12500) { ql = 1; s = 10000; }
    else if (qi < 13125) { ql = 2; s = 12500; }
    else                 { ql = 3; s = 13125; }
    const int HS[4] = {100, 50, 25, 13};
    const int Wq = HS[ql];
    int rem = qi - s;
    float refx = ((rem % Wq) + 0.5f) / (float)Wq;
    float refy = ((rem / Wq) + 0.5f) / (float)Wq;

    float e[16];
    {
        const float4* lg = (const float4*)(awlog + (size_t)bq * 128 + h * 16);
        float4 t0 = lg[0], t1 = lg[1], t2 = lg[2], t3 = lg[3];
        e[0]=t0.x; e[1]=t0.y; e[2]=t0.z; e[3]=t0.w;
        e[4]=t1.x; e[5]=t1.y; e[6]=t1.z; e[7]=t1.w;
        e[8]=t2.x; e[9]=t2.y; e[10]=t2.z; e[11]=t2.w;
        e[12]=t3.x; e[13]=t3.y; e[14]=t3.z; e[15]=t3.w;
        float m = e[0];
#pragma unroll
        for (int j = 1; j < 16; j++) m = fmaxf(m, e[j]);
        float ssum = 0.f;
#pragma unroll
        for (int j = 0; j < 16; j++) { e[j] = expf(e[j] - m); ssum += e[j]; }
        float inv = 1.0f / ssum;
#pragma unroll
        for (int j = 0; j < 16; j++) e[j] *= inv;
    }

    const float* off   = offs  + (size_t)bq * 256 + h * 32;
    const float* vbase = value + (size_t)b * L_TOK * 256 + h * 32 + lane;

    const int LH[4] = {100, 50, 25, 13};
    const int LS[4] = {0, 10000, 12500, 13125};

    float a = 0.0f;
#pragma unroll
    for (int l = 0; l < 4; l++) {
        const int   Wl = LH[l];
        const int   Sl = LS[l];
        const float Wf = (float)Wl;
#pragma unroll
        for (int p = 0; p < 4; p++) {
            float ox = off[(l * 4 + p) * 2 + 0];
            float oy = off[(l * 4 + p) * 2 + 1];
            float aw = e[l * 4 + p];
            float locx = refx + ox / Wf;
            float locy = refy + oy / Wf;
            float x = locx * Wf - 0.5f;
            float y = locy * Wf - 0.5f;
            float x0f = floorf(x), y0f = floorf(y);
            float wx1 = x - x0f,   wy1 = y - y0f;
            float wx0 = 1.0f - wx1, wy0 = 1.0f - wy1;
            int ix0 = (int)x0f, iy0 = (int)y0f;
            int ix1 = ix0 + 1,  iy1 = iy0 + 1;
            bool vx0 = (ix0 >= 0) & (ix0 < Wl);
            bool vx1 = (ix1 >= 0) & (ix1 < Wl);
            bool vy0 = (iy0 >= 0) & (iy0 < Wl);
            bool vy1 = (iy1 >= 0) & (iy1 < Wl);

            if (vy0 & vx0) a = fmaf(vbase[(size_t)(Sl + iy0 * Wl + ix0) * 256], wy0 * wx0 * aw, a);
            if (vy0 & vx1) a = fmaf(vbase[(size_t)(Sl + iy0 * Wl + ix1) * 256], wy0 * wx1 * aw, a);
            if (vy1 & vx0) a = fmaf(vbase[(size_t)(Sl + iy1 * Wl + ix0) * 256], wy1 * wx0 * aw, a);
            if (vy1 & vx1) a = fmaf(vbase[(size_t)(Sl + iy1 * Wl + ix1) * 256], wy1 * wx1 * aw, a);
        }
    }
    acc[(size_t)bq * 256 + h * 32 + lane] = a;
}

// ---------------- fused residual + LayerNorm ----------------
__global__ __launch_bounds__(256)
void ln_kernel(const float* __restrict__ a, const float* __restrict__ r,
               const float* __restrict__ g, const float* __restrict__ be,
               float* __restrict__ out)
{
    int row  = blockIdx.x * 8 + (threadIdx.x >> 5);
    int lane = threadIdx.x & 31;
    if (row >= M_TOT) return;

    const float4* pa = (const float4*)(a + (size_t)row * 256);
    const float4* pr = (const float4*)(r + (size_t)row * 256);
    float4 v0 = pa[lane],      w0 = pr[lane];
    float4 v1 = pa[32 + lane], w1 = pr[32 + lane];
    v0.x += w0.x; v0.y += w0.y; v0.z += w0.z; v0.w += w0.w;
    v1.x += w1.x; v1.y += w1.y; v1.z += w1.z; v1.w += w1.w;

    float ssum = v0.x + v0.y + v0.z + v0.w + v1.x + v1.y + v1.z + v1.w;
#pragma unroll
    for (int o = 16; o; o >>= 1) ssum += __shfl_xor_sync(0xFFFFFFFFu, ssum, o);
    float mu = ssum * (1.0f / 256.0f);

    float d0x = v0.x - mu, d0y = v0.y - mu, d0z = v0.z - mu, d0w = v0.w - mu;
    float d1x = v1.x - mu, d1y = v1.y - mu, d1z = v1.z - mu, d1w = v1.w - mu;
    float sq = d0x*d0x + d0y*d0y + d0z*d0z + d0w*d0w
             + d1x*d1x + d1y*d1y + d1z*d1z + d1w*d1w;
#pragma unroll
    for (int o = 16; o; o >>= 1) sq += __shfl_xor_sync(0xFFFFFFFFu, sq, o);
    float var = sq * (1.0f / 256.0f);
    float sc = rsqrtf(var + 1e-5f);

    const float4* pg = (const float4*)g;
    const float4* pb = (const float4*)be;
    float4 g0 = pg[lane], g1 = pg[32 + lane];
    float4 b0 = pb[lane], b1 = pb[32 + lane];

    float4 o0, o1;
    o0.x = d0x * sc * g0.x + b0.x;  o0.y = d0y * sc * g0.y + b0.y;
    o0.z = d0z * sc * g0.z + b0.z;  o0.w = d0w * sc * g0.w + b0.w;
    o1.x = d1x * sc * g1.x + b1.x;  o1.y = d1y * sc * g1.y + b1.y;
    o1.z = d1z * sc * g1.z + b1.z;  o1.w = d1w * sc * g1.w + b1.w;

    float4* po = (float4*)(out + (size_t)row * 256);
    po[lane]      = o0;
    po[32 + lane] = o1;
}

// ---------------- launch ----------------
extern "C" void kernel_launch(void* const* d_in, const int* in_sizes, int n_in,
                              void* d_out, int out_size)
{
    const float* src        = (const float*)d_in[0];
    const float* src2       = (const float*)d_in[1];
    const float* pos        = (const float*)d_in[2];
    const float* memory_pos = (const float*)d_in[3];
    const float* value_w    = (const float*)d_in[4];
    const float* value_b    = (const float*)d_in[5];
    const float* off_w      = (const float*)d_in[6];
    const float* off_b      = (const float*)d_in[7];
    const float* aw_w       = (const float*)d_in[8];
    const float* aw_b       = (const float*)d_in[9];
    const float* out_w      = (const float*)d_in[10];
    const float* out_b      = (const float*)d_in[11];
    const float* ln_g       = (const float*)d_in[12];
    const float* ln_b       = (const float*)d_in[13];
    const float* lin1_w     = (const float*)d_in[14];
    const float* lin1_b     = (const float*)d_in[15];
    const float* lin2_w     = (const float*)d_in[16];
    const float* lin2_b     = (const float*)d_in[17];
    float* outp = (float*)d_out;

    float *q, *mem, *value, *offs, *awlog, *acc, *attn, *x, *hbuf, *ffn;
    cudaGetSymbolAddress((void**)&q,     g_q);
    cudaGetSymbolAddress((void**)&mem,   g_mem);
    cudaGetSymbolAddress((void**)&value, g_value);
    cudaGetSymbolAddress((void**)&offs,  g_offs);
    cudaGetSymbolAddress((void**)&awlog, g_awlog);
    cudaGetSymbolAddress((void**)&acc,   g_acc);
    cudaGetSymbolAddress((void**)&attn,  g_attn);
    cudaGetSymbolAddress((void**)&x,     g_x);
    cudaGetSymbolAddress((void**)&hbuf,  g_h);
    cudaGetSymbolAddress((void**)&ffn,   g_ffn);

    const int n4 = M_TOT * D_MODEL / 4;
    add2_kernel<<<(n4 + 255) / 256, 256>>>(src,  pos,        q,   n4);
    add2_kernel<<<(n4 + 255) / 256, 256>>>(src2, memory_pos, mem, n4);

    dim3 blk(256);
    const int GY = (M_TOT + 127) / 128;     // 416
    dim3 g256(256 / 128,  GY);
    dim3 g128(128 / 128,  GY);
    dim3 g1024(1024 / 128, GY);

    tgemm_kernel<0><<<g256, blk>>>(mem, value_w, value_b, value, M_TOT, 256, 256);
    tgemm_kernel<0><<<g256, blk>>>(q,   off_w,   off_b,   offs,  M_TOT, 256, 256);
    tgemm_kernel<0><<<g128, blk>>>(q,   aw_w,    aw_b,    awlog, M_TOT, 128, 256);

    deform_sample_kernel<<<M_TOT, 256>>>(value, offs, awlog, acc);

    tgemm_kernel<0><<<g256, blk>>>(acc, out_w, out_b, attn, M_TOT, 256, 256);

    ln_kernel<<<(M_TOT + 7) / 8, 256>>>(attn, src, ln_g, ln_b, x);

    tgemm_kernel<1><<<g1024, blk>>>(x,    lin1_w, lin1_b, hbuf, M_TOT, 1024, 256);
    tgemm_kernel<0><<<g256,  blk>>>(hbuf, lin2_w, lin2_b, ffn,  M_TOT, 256, 1024);

    ln_kernel<<<(M_TOT + 7) / 8, 256>>>(ffn, x, ln_g, ln_b, outp);
}

// round 7
// speedup vs baseline: 2.2924x; 1.1359x over previous
#include <cuda_runtime.h>
#include <math.h>
#include <stdint.h>

// ---------------- problem constants ----------------
#define D_MODEL   256
#define N_HEADS   8
#define HEAD_DIM  32
#define L_TOK     13294
#define BATCH     4
#define M_TOT     (BATCH * L_TOK)   // 53176
#define D_FFN     1024

// ---------------- scratch (static device globals; no allocations) ----------------
__device__ float g_q    [(size_t)M_TOT * D_MODEL];
__device__ float g_mem  [(size_t)M_TOT * D_MODEL];
__device__ float g_value[(size_t)M_TOT * D_MODEL];
__device__ float g_offs [(size_t)M_TOT * D_MODEL];
__device__ float g_awlog[(size_t)M_TOT * 128];
__device__ float g_awp  [(size_t)M_TOT * 128];
__device__ float g_acc  [(size_t)M_TOT * D_MODEL];
__device__ float g_attn [(size_t)M_TOT * D_MODEL];
__device__ float g_x    [(size_t)M_TOT * D_MODEL];
__device__ float g_h    [(size_t)M_TOT * D_FFN];
__device__ float g_ffn  [(size_t)M_TOT * D_MODEL];

// ---------------- helpers ----------------
__device__ __forceinline__ void mma_tf32(float* c, const uint32_t* a, const uint32_t* b) {
    asm volatile(
        "mma.sync.aligned.m16n8k8.row.col.f32.tf32.tf32.f32 "
        "{%0,%1,%2,%3}, {%4,%5,%6,%7}, {%8,%9}, {%0,%1,%2,%3};\n"
        : "+f"(c[0]), "+f"(c[1]), "+f"(c[2]), "+f"(c[3])
        : "r"(a[0]), "r"(a[1]), "r"(a[2]), "r"(a[3]),
          "r"(b[0]), "r"(b[1]));
}

__device__ __forceinline__ void cp_async16(uint32_t smem_addr, const void* gptr) {
    asm volatile("cp.async.ca.shared.global [%0], [%1], 16;\n"
                 :: "r"(smem_addr), "l"(gptr));
}
__device__ __forceinline__ void cp_async16_guard(uint32_t smem_addr, const void* gptr, int src_bytes) {
    asm volatile("cp.async.ca.shared.global [%0], [%1], 16, %2;\n"
                 :: "r"(smem_addr), "l"(gptr), "r"(src_bytes));
}
__device__ __forceinline__ void cp_commit() {
    asm volatile("cp.async.commit_group;\n");
}
template<int N>
__device__ __forceinline__ void cp_wait() {
    asm volatile("cp.async.wait_group %0;\n" :: "n"(N));
}

// ---------------- elementwise add ----------------
__global__ void add2_kernel(const float* __restrict__ a, const float* __restrict__ b,
                            float* __restrict__ o, int n4)
{
    int i = blockIdx.x * blockDim.x + threadIdx.x;
    if (i < n4) {
        float4 x = ((const float4*)a)[i];
        float4 y = ((const float4*)b)[i];
        x.x += y.x; x.y += y.y; x.z += y.z; x.w += y.w;
        ((float4*)o)[i] = x;
    }
}

// ---------------- TF32 tensor-core GEMM, cp.async double-buffered ----------------
// C[M,N] = A[M,K] @ W[K,N] + bias (opt ReLU)
// Block tile 128x128x32, 256 threads (8 warps: 2m x 4n), warp tile 64x32.
// fp32 bits fed directly to mma.tf32 (HW truncation of low mantissa bits).
#define LDA 36
#define LDB 136
#define ASZ (128 * LDA)   // floats per A stage
#define BSZ (32 * LDB)    // floats per B stage
#define SMEM_BYTES ((2 * ASZ + 2 * BSZ) * 4)

template<int RELU>
__global__ __launch_bounds__(256)
void tgemm_kernel(const float* __restrict__ A, const float* __restrict__ W,
                  const float* __restrict__ bias, float* __restrict__ C,
                  int M, int N, int K)
{
    const int BM = 128, BN = 128, BK = 32;
    extern __shared__ float smem[];
    float* As = smem;               // [2][128][LDA]
    float* Bs = smem + 2 * ASZ;     // [2][32][LDB]

    const int tid  = threadIdx.x;
    const int lane = tid & 31;
    const int warp = tid >> 5;
    const int wm = (warp >> 2) * 64;
    const int wn = (warp & 3) * 32;
    const int grp = lane >> 2;
    const int tg  = lane & 3;
    const int m0 = blockIdx.y * BM;
    const int n0 = blockIdx.x * BN;

    uint32_t As_u = (uint32_t)__cvta_generic_to_shared(As);
    uint32_t Bs_u = (uint32_t)__cvta_generic_to_shared(Bs);

    float acc[4][4][4];
#pragma unroll
    for (int mi = 0; mi < 4; mi++)
#pragma unroll
        for (int ni = 0; ni < 4; ni++)
#pragma unroll
            for (int e = 0; e < 4; e++) acc[mi][ni][e] = 0.0f;

    const int T = K / BK;

    // fill stage st from k-offset k0
    auto fill = [&](int st, int k0) {
        uint32_t abase = As_u + (uint32_t)(st * ASZ * 4);
        uint32_t bbase = Bs_u + (uint32_t)(st * BSZ * 4);
        // A: 128 rows x 8 float4 = 1024 ops / 256 thr = 4 each
#pragma unroll
        for (int it = 0; it < 4; it++) {
            int idx = tid + it * 256;
            int r  = idx >> 3;
            int kq = idx & 7;
            int valid = (m0 + r < M) ? 16 : 0;
            cp_async16_guard(abase + (uint32_t)((r * LDA + kq * 4) * 4),
                             A + (size_t)(m0 + r) * K + k0 + kq * 4, valid);
        }
        // B: 32 k x 32 float4 = 1024 ops / 256 thr = 4 each
#pragma unroll
        for (int it = 0; it < 4; it++) {
            int idx = tid + it * 256;
            int kk = idx >> 5;
            int cq = idx & 31;
            cp_async16(bbase + (uint32_t)((kk * LDB + cq * 4) * 4),
                       W + (size_t)(k0 + kk) * N + n0 + cq * 4);
        }
        cp_commit();
    };

    fill(0, 0);

    for (int t = 0; t < T; t++) {
        if (t + 1 < T) {
            fill((t + 1) & 1, (t + 1) * BK);
            cp_wait<1>();
        } else {
            cp_wait<0>();
        }
        __syncthreads();

        const float* As_s = As + (t & 1) * ASZ;
        const float* Bs_s = Bs + (t & 1) * BSZ;

#pragma unroll
        for (int ks = 0; ks < 4; ks++) {
            const int kb = ks * 8;
            uint32_t a[4][4], b[4][2];
#pragma unroll
            for (int mi = 0; mi < 4; mi++) {
                const float* ap = As_s + (wm + mi * 16 + grp) * LDA + kb + tg;
                a[mi][0] = __float_as_uint(ap[0]);
                a[mi][2] = __float_as_uint(ap[4]);
                a[mi][1] = __float_as_uint(ap[8 * LDA]);
                a[mi][3] = __float_as_uint(ap[8 * LDA + 4]);
            }
#pragma unroll
            for (int ni = 0; ni < 4; ni++) {
                const float* bp = Bs_s + (kb + tg) * LDB + wn + ni * 8 + grp;
                b[ni][0] = __float_as_uint(bp[0]);
                b[ni][1] = __float_as_uint(bp[4 * LDB]);
            }
#pragma unroll
            for (int mi = 0; mi < 4; mi++)
#pragma unroll
                for (int ni = 0; ni < 4; ni++)
                    mma_tf32(acc[mi][ni], a[mi], b[ni]);
        }
        __syncthreads();
    }

    // epilogue: bias (+relu), float2 stores
#pragma unroll
    for (int mi = 0; mi < 4; mi++) {
        int r0 = m0 + wm + mi * 16 + grp;
        int r1 = r0 + 8;
#pragma unroll
        for (int ni = 0; ni < 4; ni++) {
            int col = n0 + wn + ni * 8 + tg * 2;
            float bx = bias[col], by = bias[col + 1];
            float* cc = acc[mi][ni];
            if (r0 < M) {
                float2 o; o.x = cc[0] + bx; o.y = cc[1] + by;
                if (RELU) { o.x = fmaxf(o.x, 0.f); o.y = fmaxf(o.y, 0.f); }
                *(float2*)(C + (size_t)r0 * N + col) = o;
            }
            if (r1 < M) {
                float2 o; o.x = cc[2] + bx; o.y = cc[3] + by;
                if (RELU) { o.x = fmaxf(o.x, 0.f); o.y = fmaxf(o.y, 0.f); }
                *(float2*)(C + (size_t)r1 * N + col) = o;
            }
        }
    }
}

// ---------------- softmax over 16 logits per (bq, head) ----------------
__global__ void softmax16_kernel(const float* __restrict__ logits,
                                 float* __restrict__ probs, int n)
{
    int i = blockIdx.x * blockDim.x + threadIdx.x;
    if (i >= n) return;
    const float4* in = (const float4*)(logits + (size_t)i * 16);
    float4 t0 = in[0], t1 = in[1], t2 = in[2], t3 = in[3];
    float e[16] = {t0.x,t0.y,t0.z,t0.w, t1.x,t1.y,t1.z,t1.w,
                   t2.x,t2.y,t2.z,t2.w, t3.x,t3.y,t3.z,t3.w};
    float m = e[0];
#pragma unroll
    for (int j = 1; j < 16; j++) m = fmaxf(m, e[j]);
    float s = 0.f;
#pragma unroll
    for (int j = 0; j < 16; j++) { e[j] = expf(e[j] - m); s += e[j]; }
    float inv = 1.0f / s;
    float4* out = (float4*)(probs + (size_t)i * 16);
    out[0] = make_float4(e[0]*inv,  e[1]*inv,  e[2]*inv,  e[3]*inv);
    out[1] = make_float4(e[4]*inv,  e[5]*inv,  e[6]*inv,  e[7]*inv);
    out[2] = make_float4(e[8]*inv,  e[9]*inv,  e[10]*inv, e[11]*inv);
    out[3] = make_float4(e[12]*inv, e[13]*inv, e[14]*inv, e[15]*inv);
}

// ---------------- deformable attention sampling (probs precomputed) ----------------
__global__ __launch_bounds__(256)
void deform_sample_kernel(const float* __restrict__ value,
                          const float* __restrict__ offs,
                          const float* __restrict__ awp,
                          float* __restrict__ acc)
{
    const int bq = blockIdx.x;
    if (bq >= M_TOT) return;
    const int h    = threadIdx.x >> 5;
    const int lane = threadIdx.x & 31;

    const int b  = bq / L_TOK;
    const int qi = bq - b * L_TOK;

    int ql, s;
    if      (qi < 10000) { ql = 0; s = 0;     }
    else if (qi < 12500) { ql = 1; s = 10000; }
    else if (qi < 13125) { ql = 2; s = 12500; }
    else                 { ql = 3; s = 13125; }
    const int HS[4] = {100, 50, 25, 13};
    const int Wq = HS[ql];
    int rem = qi - s;
    float refx = ((rem % Wq) + 0.5f) / (float)Wq;
    float refy = ((rem / Wq) + 0.5f) / (float)Wq;

    float e[16];
    {
        const float4* lg = (const float4*)(awp + (size_t)bq * 128 + h * 16);
        float4 t0 = lg[0], t1 = lg[1], t2 = lg[2], t3 = lg[3];
        e[0]=t0.x; e[1]=t0.y; e[2]=t0.z; e[3]=t0.w;
        e[4]=t1.x; e[5]=t1.y; e[6]=t1.z; e[7]=t1.w;
        e[8]=t2.x; e[9]=t2.y; e[10]=t2.z; e[11]=t2.w;
        e[12]=t3.x; e[13]=t3.y; e[14]=t3.z; e[15]=t3.w;
    }

    const float* off   = offs  + (size_t)bq * 256 + h * 32;
    const float* vbase = value + (size_t)b * L_TOK * 256 + h * 32 + lane;

    const int LH[4] = {100, 50, 25, 13};
    const int LS[4] = {0, 10000, 12500, 13125};

    float a = 0.0f;
#pragma unroll
    for (int l = 0; l < 4; l++) {
        const int   Wl = LH[l];
        const int   Sl = LS[l];
        const float Wf = (float)Wl;
#pragma unroll
        for (int p = 0; p < 4; p++) {
            float ox = off[(l * 4 + p) * 2 + 0];
            float oy = off[(l * 4 + p) * 2 + 1];
            float aw = e[l * 4 + p];
            float locx = refx + ox / Wf;
            float locy = refy + oy / Wf;
            float x = locx * Wf - 0.5f;
            float y = locy * Wf - 0.5f;
            float x0f = floorf(x), y0f = floorf(y);
            float wx1 = x - x0f,   wy1 = y - y0f;
            float wx0 = 1.0f - wx1, wy0 = 1.0f - wy1;
            int ix0 = (int)x0f, iy0 = (int)y0f;
            int ix1 = ix0 + 1,  iy1 = iy0 + 1;
            bool vx0 = (ix0 >= 0) & (ix0 < Wl);
            bool vx1 = (ix1 >= 0) & (ix1 < Wl);
            bool vy0 = (iy0 >= 0) & (iy0 < Wl);
            bool vy1 = (iy1 >= 0) & (iy1 < Wl);

            if (vy0 & vx0) a = fmaf(vbase[(size_t)(Sl + iy0 * Wl + ix0) * 256], wy0 * wx0 * aw, a);
            if (vy0 & vx1) a = fmaf(vbase[(size_t)(Sl + iy0 * Wl + ix1) * 256], wy0 * wx1 * aw, a);
            if (vy1 & vx0) a = fmaf(vbase[(size_t)(Sl + iy1 * Wl + ix0) * 256], wy1 * wx0 * aw, a);
            if (vy1 & vx1) a = fmaf(vbase[(size_t)(Sl + iy1 * Wl + ix1) * 256], wy1 * wx1 * aw, a);
        }
    }
    acc[(size_t)bq * 256 + h * 32 + lane] = a;
}

// ---------------- fused residual + LayerNorm ----------------
__global__ __launch_bounds__(256)
void ln_kernel(const float* __restrict__ a, const float* __restrict__ r,
               const float* __restrict__ g, const float* __restrict__ be,
               float* __restrict__ out)
{
    int row  = blockIdx.x * 8 + (threadIdx.x >> 5);
    int lane = threadIdx.x & 31;
    if (row >= M_TOT) return;

    const float4* pa = (const float4*)(a + (size_t)row * 256);
    const float4* pr = (const float4*)(r + (size_t)row * 256);
    float4 v0 = pa[lane],      w0 = pr[lane];
    float4 v1 = pa[32 + lane], w1 = pr[32 + lane];
    v0.x += w0.x; v0.y += w0.y; v0.z += w0.z; v0.w += w0.w;
    v1.x += w1.x; v1.y += w1.y; v1.z += w1.z; v1.w += w1.w;

    float ssum = v0.x + v0.y + v0.z + v0.w + v1.x + v1.y + v1.z + v1.w;
#pragma unroll
    for (int o = 16; o; o >>= 1) ssum += __shfl_xor_sync(0xFFFFFFFFu, ssum, o);
    float mu = ssum * (1.0f / 256.0f);

    float d0x = v0.x - mu, d0y = v0.y - mu, d0z = v0.z - mu, d0w = v0.w - mu;
    float d1x = v1.x - mu, d1y = v1.y - mu, d1z = v1.z - mu, d1w = v1.w - mu;
    float sq = d0x*d0x + d0y*d0y + d0z*d0z + d0w*d0w
             + d1x*d1x + d1y*d1y + d1z*d1z + d1w*d1w;
#pragma unroll
    for (int o = 16; o; o >>= 1) sq += __shfl_xor_sync(0xFFFFFFFFu, sq, o);
    float var = sq * (1.0f / 256.0f);
    float sc = rsqrtf(var + 1e-5f);

    const float4* pg = (const float4*)g;
    const float4* pb = (const float4*)be;
    float4 g0 = pg[lane], g1 = pg[32 + lane];
    float4 b0 = pb[lane], b1 = pb[32 + lane];

    float4 o0, o1;
    o0.x = d0x * sc * g0.x + b0.x;  o0.y = d0y * sc * g0.y + b0.y;
    o0.z = d0z * sc * g0.z + b0.z;  o0.w = d0w * sc * g0.w + b0.w;
    o1.x = d1x * sc * g1.x + b1.x;  o1.y = d1y * sc * g1.y + b1.y;
    o1.z = d1z * sc * g1.z + b1.z;  o1.w = d1w * sc * g1.w + b1.w;

    float4* po = (float4*)(out + (size_t)row * 256);
    po[lane]      = o0;
    po[32 + lane] = o1;
}

// ---------------- launch ----------------
extern "C" void kernel_launch(void* const* d_in, const int* in_sizes, int n_in,
                              void* d_out, int out_size)
{
    const float* src        = (const float*)d_in[0];
    const float* src2       = (const float*)d_in[1];
    const float* pos        = (const float*)d_in[2];
    const float* memory_pos = (const float*)d_in[3];
    const float* value_w    = (const float*)d_in[4];
    const float* value_b    = (const float*)d_in[5];
    const float* off_w      = (const float*)d_in[6];
    const float* off_b      = (const float*)d_in[7];
    const float* aw_w       = (const float*)d_in[8];
    const float* aw_b       = (const float*)d_in[9];
    const float* out_w      = (const float*)d_in[10];
    const float* out_b      = (const float*)d_in[11];
    const float* ln_g       = (const float*)d_in[12];
    const float* ln_b       = (const float*)d_in[13];
    const float* lin1_w     = (const float*)d_in[14];
    const float* lin1_b     = (const float*)d_in[15];
    const float* lin2_w     = (const float*)d_in[16];
    const float* lin2_b     = (const float*)d_in[17];
    float* outp = (float*)d_out;

    float *q, *mem, *value, *offs, *awlog, *awp, *acc, *attn, *x, *hbuf, *ffn;
    cudaGetSymbolAddress((void**)&q,     g_q);
    cudaGetSymbolAddress((void**)&mem,   g_mem);
    cudaGetSymbolAddress((void**)&value, g_value);
    cudaGetSymbolAddress((void**)&offs,  g_offs);
    cudaGetSymbolAddress((void**)&awlog, g_awlog);
    cudaGetSymbolAddress((void**)&awp,   g_awp);
    cudaGetSymbolAddress((void**)&acc,   g_acc);
    cudaGetSymbolAddress((void**)&attn,  g_attn);
    cudaGetSymbolAddress((void**)&x,     g_x);
    cudaGetSymbolAddress((void**)&hbuf,  g_h);
    cudaGetSymbolAddress((void**)&ffn,   g_ffn);

    cudaFuncSetAttribute(tgemm_kernel<0>, cudaFuncAttributeMaxDynamicSharedMemorySize, SMEM_BYTES);
    cudaFuncSetAttribute(tgemm_kernel<1>, cudaFuncAttributeMaxDynamicSharedMemorySize, SMEM_BYTES);

    const int n4 = M_TOT * D_MODEL / 4;
    add2_kernel<<<(n4 + 255) / 256, 256>>>(src,  pos,        q,   n4);
    add2_kernel<<<(n4 + 255) / 256, 256>>>(src2, memory_pos, mem, n4);

    dim3 blk(256);
    const int GY = (M_TOT + 127) / 128;     // 416
    dim3 g256(256 / 128,  GY);
    dim3 g128(128 / 128,  GY);
    dim3 g1024(1024 / 128, GY);

    tgemm_kernel<0><<<g256, blk, SMEM_BYTES>>>(mem, value_w, value_b, value, M_TOT, 256, 256);
    tgemm_kernel<0><<<g256, blk, SMEM_BYTES>>>(q,   off_w,   off_b,   offs,  M_TOT, 256, 256);
    tgemm_kernel<0><<<g128, blk, SMEM_BYTES>>>(q,   aw_w,    aw_b,    awlog, M_TOT, 128, 256);

    const int nsm = M_TOT * N_HEADS;
    softmax16_kernel<<<(nsm + 255) / 256, 256>>>(awlog, awp, nsm);

    deform_sample_kernel<<<M_TOT, 256>>>(value, offs, awp, acc);

    tgemm_kernel<0><<<g256, blk, SMEM_BYTES>>>(acc, out_w, out_b, attn, M_TOT, 256, 256);

    ln_kernel<<<(M_TOT + 7) / 8, 256>>>(attn, src, ln_g, ln_b, x);

    tgemm_kernel<1><<<g1024, blk, SMEM_BYTES>>>(x,    lin1_w, lin1_b, hbuf, M_TOT, 1024, 256);
    tgemm_kernel<0><<<g256,  blk, SMEM_BYTES>>>(hbuf, lin2_w, lin2_b, ffn,  M_TOT, 256, 1024);

    ln_kernel<<<(M_TOT + 7) / 8, 256>>>(ffn, x, ln_g, ln_b, outp);
}